// round 15
// baseline (speedup 1.0000x reference)
#include <cuda_runtime.h>
#include <cuda_bf16.h>
#include <stdint.h>
#include <math.h>

typedef unsigned int u32;

#define B_  2
#define T_  2048
#define C_  1024
#define H_  16
#define HS_ 64
#define NB_ 32
#define BLK_ 64
#define NSEL_ 8
#define WSZ_ 128
#define M_  (B_*T_)

// ---------------- device scratch ----------------
__device__ float g_q[B_*T_*C_];
__device__ float g_k[B_*T_*C_];
__device__ float g_v[B_*T_*C_];
__device__ float g_attn[B_*T_*C_];
__device__ float g_gates[B_*T_*3];
__device__ float g_krep[B_*H_*NB_*HS_];
__device__ float g_vcmp[B_*H_*NB_*HS_];
__device__ float g_qbar[B_*H_*HS_];
__device__ float g_qbar_part[B_*H_*8*HS_];
__device__ int   g_topidx[B_*H_*NSEL_];
__device__ float g_selk[B_*H_*NSEL_*BLK_*HS_];
__device__ float g_selv[B_*H_*NSEL_*BLK_*HS_];

__device__ __nv_bfloat16 g_xh[M_*C_];
__device__ __nv_bfloat16 g_xl[M_*C_];
__device__ __nv_bfloat16 g_ah[M_*C_];
__device__ __nv_bfloat16 g_al[M_*C_];
__device__ __nv_bfloat16 g_wh[C_*C_];
__device__ __nv_bfloat16 g_wl[C_*C_];

// ---------------- helpers ----------------
__device__ __forceinline__ u32 smem_u32(const void* p) {
    u32 a;
    asm("{ .reg .u64 t; cvta.to.shared.u64 t, %1; cvt.u32.u64 %0, t; }" : "=r"(a) : "l"(p));
    return a;
}
__device__ __forceinline__ void cp16s(u32 saddr, const void* g) {
    asm volatile("cp.async.cg.shared.global [%0], [%1], 16;\n" :: "r"(saddr), "l"(g));
}
__device__ __forceinline__ void ldsm_x4(u32* r, u32 addr) {
    asm volatile("ldmatrix.sync.aligned.m8n8.x4.shared.b16 {%0,%1,%2,%3}, [%4];"
        : "=r"(r[0]), "=r"(r[1]), "=r"(r[2]), "=r"(r[3]) : "r"(addr));
}
__device__ __forceinline__ void ldsm_x4_t(u32* r, u32 addr) {
    asm volatile("ldmatrix.sync.aligned.m8n8.x4.trans.shared.b16 {%0,%1,%2,%3}, [%4];"
        : "=r"(r[0]), "=r"(r[1]), "=r"(r[2]), "=r"(r[3]) : "r"(addr));
}
__device__ __forceinline__ void mma16816(float* d, const u32* a, const u32* b) {
    asm volatile(
        "mma.sync.aligned.m16n8k16.row.col.f32.bf16.bf16.f32 "
        "{%0,%1,%2,%3},{%4,%5,%6,%7},{%8,%9},{%0,%1,%2,%3};"
        : "+f"(d[0]), "+f"(d[1]), "+f"(d[2]), "+f"(d[3])
        : "r"(a[0]), "r"(a[1]), "r"(a[2]), "r"(a[3]), "r"(b[0]), "r"(b[1]));
}
__device__ __forceinline__ u32 pack_hi2(float a, float b) {
    __nv_bfloat162 t = __halves2bfloat162(__float2bfloat16(a), __float2bfloat16(b));
    return *(u32*)&t;
}
__device__ __forceinline__ u32 pack_lo2(float a, float b) {
    __nv_bfloat16 ha = __float2bfloat16(a), hb = __float2bfloat16(b);
    __nv_bfloat162 t = __halves2bfloat162(
        __float2bfloat16(a - __bfloat162float(ha)),
        __float2bfloat16(b - __bfloat162float(hb)));
    return *(u32*)&t;
}

// ---------------- fp32 -> bf16 hi/lo split ----------------
__global__ void split_kernel(const float* __restrict__ src,
                             __nv_bfloat16* __restrict__ hi,
                             __nv_bfloat16* __restrict__ lo, int n4)
{
    int i = blockIdx.x * blockDim.x + threadIdx.x;
    if (i >= n4) return;
    float4 v = ((const float4*)src)[i];
    __nv_bfloat16 h0 = __float2bfloat16(v.x);
    __nv_bfloat16 h1 = __float2bfloat16(v.y);
    __nv_bfloat16 h2 = __float2bfloat16(v.z);
    __nv_bfloat16 h3 = __float2bfloat16(v.w);
    __nv_bfloat16 l0 = __float2bfloat16(v.x - __bfloat162float(h0));
    __nv_bfloat16 l1 = __float2bfloat16(v.y - __bfloat162float(h1));
    __nv_bfloat16 l2 = __float2bfloat16(v.z - __bfloat162float(h2));
    __nv_bfloat16 l3 = __float2bfloat16(v.w - __bfloat162float(h3));
    __nv_bfloat162* hp = (__nv_bfloat162*)hi;
    __nv_bfloat162* lp = (__nv_bfloat162*)lo;
    hp[i*2]   = __halves2bfloat162(h0, h1);
    hp[i*2+1] = __halves2bfloat162(h2, h3);
    lp[i*2]   = __halves2bfloat162(l0, l1);
    lp[i*2+1] = __halves2bfloat162(l2, l3);
}

// ---------------- GEMM: BK=64, 2-stage cp.async, term-major MMAs, dynamic smem ----------------
#define BK4 64
#define A_ROW 72            // 64 + 8 pad (bf16 elems)
#define B_ROW 136           // 128 + 8 pad
#define A_STG (128 * A_ROW) // 9216 elems per plane per stage
#define B_STG (64 * B_ROW)  // 8704 elems
#define GEMM_SMEM ((2 * A_STG + 2 * B_STG) * 2 * 2)   // 143360 bytes

__global__ void __launch_bounds__(256) gemm_bf16x3_kernel(
    const __nv_bfloat16* __restrict__ Ah, const __nv_bfloat16* __restrict__ Al,
    const __nv_bfloat16* __restrict__ Bh, const __nv_bfloat16* __restrict__ Bl,
    const float* __restrict__ bias, float* __restrict__ C,
    int M, int N, int K)
{
    extern __shared__ __align__(16) __nv_bfloat16 sm[];

    int tid = threadIdx.x;
    int lane = tid & 31, warp = tid >> 5;
    int wm = warp >> 1, wn = warp & 1;
    int bm0 = blockIdx.y * 128, bn0 = blockIdx.x * 128;

    // A: 128 rows x 64 cols -> 4 x 16B chunks/thread/plane
    int ar = tid >> 1,  ac = (tid & 1) << 3;     // base col 0 or 8
    // B: 64 rows x 128 cols -> 4 chunks/thread/plane
    int br = tid >> 4,  bc = (tid & 15) << 3;    // base row 0..15
    const __nv_bfloat16* pAh = Ah + (size_t)(bm0 + ar) * K + ac;
    const __nv_bfloat16* pAl = Al + (size_t)(bm0 + ar) * K + ac;
    const __nv_bfloat16* pBh = Bh + (size_t)br * N + bn0 + bc;
    const __nv_bfloat16* pBl = Bl + (size_t)br * N + bn0 + bc;
    const u32 aoB = (u32)(ar * A_ROW + ac) * 2;
    const u32 boB = (u32)(br * B_ROW + bc) * 2;
    const u32 smB = smem_u32(sm);
    const u32 STG_B = (2 * A_STG + 2 * B_STG) * 2;   // bytes per stage
    const u32 AH_O = 0;
    const u32 AL_O = A_STG * 2;
    const u32 BH_O = 2 * A_STG * 2;
    const u32 BL_O = (2 * A_STG + B_STG) * 2;

    float acc[2][8][4];
#pragma unroll
    for (int mt = 0; mt < 2; mt++)
#pragma unroll
        for (int nt = 0; nt < 8; nt++)
#pragma unroll
            for (int r = 0; r < 4; r++) acc[mt][nt][r] = 0.f;

    const int NK = K / BK4;   // 16

#define LOADK(stage, kc) do { \
    u32 sb = smB + (u32)(stage) * STG_B; \
    int ko = (kc) * BK4; \
    _Pragma("unroll") \
    for (int q = 0; q < 4; q++) { \
        cp16s(sb + AH_O + aoB + q * 32, pAh + ko + q * 16); \
        cp16s(sb + AL_O + aoB + q * 32, pAl + ko + q * 16); \
        cp16s(sb + BH_O + boB + (u32)q * 16 * B_ROW * 2, pBh + (size_t)(ko + q * 16) * N); \
        cp16s(sb + BL_O + boB + (u32)q * 16 * B_ROW * 2, pBl + (size_t)(ko + q * 16) * N); \
    } \
    asm volatile("cp.async.commit_group;\n" ::: "memory"); \
} while (0)

    LOADK(0, 0);

    for (int k = 0; k < NK; k++) {
        int cur = k & 1;
        if (k + 1 < NK) {
            LOADK(1 - cur, k + 1);
            asm volatile("cp.async.wait_group 1;\n" ::: "memory");
        } else {
            asm volatile("cp.async.wait_group 0;\n" ::: "memory");
        }
        __syncthreads();

        u32 sb = smB + (u32)cur * STG_B;
#pragma unroll
        for (int ks = 0; ks < 4; ks++) {
            u32 ah[2][4], al[2][4];
#pragma unroll
            for (int mt = 0; mt < 2; mt++) {
                int row = wm * 32 + mt * 16 + (lane & 15);
                int col = ks * 16 + ((lane >> 4) << 3);
                u32 o = (u32)(row * A_ROW + col) * 2;
                ldsm_x4(ah[mt], sb + AH_O + o);
                ldsm_x4(al[mt], sb + AL_O + o);
            }
#pragma unroll
            for (int np = 0; np < 4; np++) {
                int krow = ks * 16 + (lane & 7) + (lane & 8);
                int ncol = wn * 64 + np * 16 + ((lane >> 4) << 3);
                u32 o = (u32)(krow * B_ROW + ncol) * 2;
                u32 bh[4], bl[4];
                ldsm_x4_t(bh, sb + BH_O + o);
                ldsm_x4_t(bl, sb + BL_O + o);
#pragma unroll
                for (int mt = 0; mt < 2; mt++)
#pragma unroll
                    for (int t = 0; t < 2; t++)
                        mma16816(acc[mt][np * 2 + t], ah[mt], &bh[t * 2]);
#pragma unroll
                for (int mt = 0; mt < 2; mt++)
#pragma unroll
                    for (int t = 0; t < 2; t++)
                        mma16816(acc[mt][np * 2 + t], ah[mt], &bl[t * 2]);
#pragma unroll
                for (int mt = 0; mt < 2; mt++)
#pragma unroll
                    for (int t = 0; t < 2; t++)
                        mma16816(acc[mt][np * 2 + t], al[mt], &bh[t * 2]);
            }
        }
        __syncthreads();
    }
#undef LOADK

    int grp = lane >> 2, tg = lane & 3;
#pragma unroll
    for (int mt = 0; mt < 2; mt++) {
#pragma unroll
        for (int nt = 0; nt < 8; nt++) {
            int row = bm0 + wm * 32 + mt * 16 + grp;
            int col = bn0 + wn * 64 + nt * 8 + tg * 2;
            float b0 = bias[col], b1 = bias[col + 1];
            float* c0 = C + (size_t)row * N + col;
            float* c1 = C + (size_t)(row + 8) * N + col;
            c0[0] = acc[mt][nt][0] + b0;
            c0[1] = acc[mt][nt][1] + b1;
            c1[0] = acc[mt][nt][2] + b0;
            c1[1] = acc[mt][nt][3] + b1;
        }
    }
}

// ---------------- gates ----------------
__global__ void gates_kernel(const float* __restrict__ x,
                             const float* __restrict__ Wg,
                             const float* __restrict__ bg)
{
    int gidx = blockIdx.x * blockDim.x + threadIdx.x;
    int w = gidx >> 5, lane = gidx & 31;
    if (w >= B_ * T_) return;
    const float* xr = x + (size_t)w * C_;
    float s0 = 0, s1 = 0, s2 = 0;
    for (int c = lane; c < C_; c += 32) {
        float xv = xr[c];
        s0 += xv * Wg[c * 3 + 0];
        s1 += xv * Wg[c * 3 + 1];
        s2 += xv * Wg[c * 3 + 2];
    }
#pragma unroll
    for (int o = 16; o; o >>= 1) {
        s0 += __shfl_xor_sync(0xffffffffu, s0, o);
        s1 += __shfl_xor_sync(0xffffffffu, s1, o);
        s2 += __shfl_xor_sync(0xffffffffu, s2, o);
    }
    if (lane == 0) {
        s0 += bg[0]; s1 += bg[1]; s2 += bg[2];
        float mx = fmaxf(s0, fmaxf(s1, s2));
        float e0 = __expf(s0 - mx), e1 = __expf(s1 - mx), e2 = __expf(s2 - mx);
        float inv = 1.f / (e0 + e1 + e2);
        g_gates[w * 3 + 0] = e0 * inv;
        g_gates[w * 3 + 1] = e1 * inv;
        g_gates[w * 3 + 2] = e2 * inv;
    }
}

// ---------------- per-block mean of K and V ----------------
__global__ void blockmean_kernel()
{
    int idx = blockIdx.x * blockDim.x + threadIdx.x;
    if (idx >= B_ * H_ * NB_ * HS_) return;
    int d = idx & 63;
    int n = (idx >> 6) & 31;
    int h = (idx >> 11) & 15;
    int b = idx >> 15;
    const float* kp = g_k + ((size_t)(b * T_ + n * BLK_)) * C_ + h * HS_ + d;
    const float* vp = g_v + ((size_t)(b * T_ + n * BLK_)) * C_ + h * HS_ + d;
    float sk = 0.f, sv = 0.f;
    for (int j = 0; j < BLK_; j++) {
        sk += kp[(size_t)j * C_];
        sv += vp[(size_t)j * C_];
    }
    g_krep[idx] = sk * (1.f / BLK_);
    g_vcmp[idx] = sv * (1.f / BLK_);
}

// ---------------- qbar phase 1 ----------------
__global__ void qbar1_kernel()
{
    int bh = blockIdx.x >> 3, chunk = blockIdx.x & 7;
    int b = bh >> 4, h = bh & 15;
    int warp = threadIdx.x >> 5, lane = threadIdx.x & 31;
    float a0 = 0.f, a1 = 0.f;
    int t0 = chunk * 256;
    for (int t = t0 + warp; t < t0 + 256; t += 8) {
        const float* qr = g_q + ((size_t)(b * T_ + t)) * C_ + h * HS_;
        float x0 = qr[lane], x1 = qr[lane + 32];
        float ss = x0 * x0 + x1 * x1;
#pragma unroll
        for (int o = 16; o; o >>= 1) ss += __shfl_xor_sync(0xffffffffu, ss, o);
        float inv = 1.f / fmaxf(sqrtf(ss), 1e-8f);
        a0 += x0 * inv;
        a1 += x1 * inv;
    }
    __shared__ float acc[64];
    if (threadIdx.x < 64) acc[threadIdx.x] = 0.f;
    __syncthreads();
    atomicAdd(&acc[lane], a0);
    atomicAdd(&acc[lane + 32], a1);
    __syncthreads();
    if (threadIdx.x < 64)
        g_qbar_part[(size_t)blockIdx.x * 64 + threadIdx.x] = acc[threadIdx.x];
}

// ---------------- qbar phase 2 ----------------
__global__ void qbar2_kernel()
{
    int bh = blockIdx.x, d = threadIdx.x;
    float s = 0.f;
#pragma unroll
    for (int c = 0; c < 8; c++)
        s += g_qbar_part[((size_t)bh * 8 + c) * 64 + d];
    g_qbar[bh * 64 + d] = s;
}

// ---------------- top-8 ----------------
__global__ void topk_kernel()
{
    int bh = blockIdx.x;
    int n = threadIdx.x;
    const float* kr = g_krep + ((size_t)bh * NB_ + n) * HS_;
    const float* qb = g_qbar + (size_t)bh * HS_;
    float dot = 0.f, ss = 0.f;
    for (int d = 0; d < HS_; d++) {
        float kv = kr[d];
        dot += kv * qb[d];
        ss += kv * kv;
    }
    float score = dot / fmaxf(sqrtf(ss), 1e-8f);
    __shared__ float sc[NB_];
    sc[n] = score;
    __syncthreads();
    if (n == 0) {
        bool used[NB_];
        for (int m = 0; m < NB_; m++) used[m] = false;
        for (int s = 0; s < NSEL_; s++) {
            float best = -1e30f; int bi = 0;
            for (int m = 0; m < NB_; m++)
                if (!used[m] && sc[m] > best) { best = sc[m]; bi = m; }
            used[bi] = true;
            g_topidx[bh * NSEL_ + s] = bi;
        }
    }
}

// ---------------- gather selected K/V ----------------
__global__ void gather_kernel()
{
    int idx = blockIdx.x * blockDim.x + threadIdx.x;
    if (idx >= B_ * H_ * NSEL_ * BLK_ * HS_) return;
    int d = idx & 63;
    int s = (idx >> 6) & 511;
    int h = (idx >> 15) & 15;
    int b = idx >> 19;
    int blk = g_topidx[(b * H_ + h) * NSEL_ + (s >> 6)];
    int row = blk * BLK_ + (s & 63);
    size_t src = ((size_t)(b * T_ + row)) * C_ + h * HS_ + d;
    g_selk[idx] = g_k[src];
    g_selv[idx] = g_v[src];
}

// ---------------- merged tensor-core attention (all 3 modes per block) ----------------
__global__ void __launch_bounds__(128) tc_attn_all()
{
    const int qt = blockIdx.x;
    const int h = blockIdx.y, b = blockIdx.z;
    const int q0 = qt * 64;
    const int lane = threadIdx.x & 31, warp = threadIdx.x >> 5;
    const int g = lane >> 2, tg = lane & 3;
    const int i0 = q0 + warp * 16 + g;
    const int i1 = i0 + 8;

    __shared__ __align__(16) __nv_bfloat16 sKh[64][72];
    __shared__ __align__(16) __nv_bfloat16 sKl[64][72];
    __shared__ __align__(16) __nv_bfloat16 sVh[64][72];
    __shared__ __align__(16) __nv_bfloat16 sVl[64][72];

    u32 qh[4][4], ql[4][4];
    {
        const float* qr0 = g_q + ((size_t)(b * T_ + i0)) * C_ + h * HS_;
        const float* qr1 = g_q + ((size_t)(b * T_ + i1)) * C_ + h * HS_;
#pragma unroll
        for (int kk = 0; kk < 4; kk++) {
            int c = kk * 16 + tg * 2;
            qh[kk][0] = pack_hi2(qr0[c], qr0[c + 1]);
            ql[kk][0] = pack_lo2(qr0[c], qr0[c + 1]);
            qh[kk][1] = pack_hi2(qr1[c], qr1[c + 1]);
            ql[kk][1] = pack_lo2(qr1[c], qr1[c + 1]);
            qh[kk][2] = pack_hi2(qr0[c + 8], qr0[c + 9]);
            ql[kk][2] = pack_lo2(qr0[c + 8], qr0[c + 9]);
            qh[kk][3] = pack_hi2(qr1[c + 8], qr1[c + 9]);
            ql[kk][3] = pack_lo2(qr1[c + 8], qr1[c + 9]);
        }
    }

    float Of[8][4];
#pragma unroll
    for (int nt = 0; nt < 8; nt++)
#pragma unroll
        for (int r = 0; r < 4; r++) Of[nt][r] = 0.f;

    for (int mode = 0; mode < 3; mode++) {
        float O[8][4];
#pragma unroll
        for (int nt = 0; nt < 8; nt++)
#pragma unroll
            for (int r = 0; r < 4; r++) O[nt][r] = 0.f;
        float m0 = -1e30f, m1 = -1e30f, l0 = 0.f, l1 = 0.f;

        int kt0, kt1, krows, ntmax;
        if (mode == 0)      { kt0 = (qt >= 2 ? qt - 2 : 0); kt1 = qt; krows = 64; ntmax = 8; }
        else if (mode == 1) { kt0 = 0; kt1 = (qt < 7 ? qt : 7);      krows = 64; ntmax = 8; }
        else                { kt0 = 0; kt1 = 0;                       krows = 32; ntmax = 4; }

        for (int kt = kt0; kt <= kt1; kt++) {
            const float* ksrc; const float* vsrc; int kstride;
            if (mode == 0) {
                ksrc = g_k + ((size_t)(b * T_ + kt * 64)) * C_ + h * HS_;
                vsrc = g_v + ((size_t)(b * T_ + kt * 64)) * C_ + h * HS_;
                kstride = C_;
            } else if (mode == 1) {
                ksrc = g_selk + ((size_t)((b * H_ + h) * 512 + kt * 64)) * HS_;
                vsrc = g_selv + ((size_t)((b * H_ + h) * 512 + kt * 64)) * HS_;
                kstride = HS_;
            } else {
                ksrc = g_krep + ((size_t)(b * H_ + h) * NB_) * HS_;
                vsrc = g_vcmp + ((size_t)(b * H_ + h) * NB_) * HS_;
                kstride = HS_;
            }
            for (int idx = threadIdx.x; idx < krows * 16; idx += 128) {
                int r = idx >> 4, c = (idx & 15) * 4;
                float4 kv = *(const float4*)(ksrc + (size_t)r * kstride + c);
                float4 vv = *(const float4*)(vsrc + (size_t)r * kstride + c);
                __nv_bfloat16 h0 = __float2bfloat16(kv.x), h1 = __float2bfloat16(kv.y);
                __nv_bfloat16 h2 = __float2bfloat16(kv.z), h3 = __float2bfloat16(kv.w);
                sKh[r][c] = h0; sKh[r][c+1] = h1; sKh[r][c+2] = h2; sKh[r][c+3] = h3;
                sKl[r][c]   = __float2bfloat16(kv.x - __bfloat162float(h0));
                sKl[r][c+1] = __float2bfloat16(kv.y - __bfloat162float(h1));
                sKl[r][c+2] = __float2bfloat16(kv.z - __bfloat162float(h2));
                sKl[r][c+3] = __float2bfloat16(kv.w - __bfloat162float(h3));
                h0 = __float2bfloat16(vv.x); h1 = __float2bfloat16(vv.y);
                h2 = __float2bfloat16(vv.z); h3 = __float2bfloat16(vv.w);
                sVh[r][c] = h0; sVh[r][c+1] = h1; sVh[r][c+2] = h2; sVh[r][c+3] = h3;
                sVl[r][c]   = __float2bfloat16(vv.x - __bfloat162float(h0));
                sVl[r][c+1] = __float2bfloat16(vv.y - __bfloat162float(h1));
                sVl[r][c+2] = __float2bfloat16(vv.z - __bfloat162float(h2));
                sVl[r][c+3] = __float2bfloat16(vv.w - __bfloat162float(h3));
            }
            __syncthreads();

            float S[8][4];
#pragma unroll
            for (int nt = 0; nt < 8; nt++)
#pragma unroll
                for (int r = 0; r < 4; r++) S[nt][r] = 0.f;

#pragma unroll
            for (int kk = 0; kk < 4; kk++) {
                for (int ntp = 0; ntp < ntmax / 2; ntp++) {
                    int row = ntp * 16 + ((lane >> 4) << 3) + (lane & 7);
                    int col = kk * 16 + (((lane >> 3) & 1) << 3);
                    u32 kh2[4], kl2[4];
                    ldsm_x4(kh2, smem_u32(&sKh[row][col]));
                    ldsm_x4(kl2, smem_u32(&sKl[row][col]));
#pragma unroll
                    for (int t = 0; t < 2; t++)
                        mma16816(S[ntp * 2 + t], qh[kk], &kh2[t * 2]);
#pragma unroll
                    for (int t = 0; t < 2; t++)
                        mma16816(S[ntp * 2 + t], qh[kk], &kl2[t * 2]);
#pragma unroll
                    for (int t = 0; t < 2; t++)
                        mma16816(S[ntp * 2 + t], ql[kk], &kh2[t * 2]);
                }
            }

            const int tilebase = kt * 64;
            for (int nt = 0; nt < ntmax; nt++) {
                int c0 = tilebase + nt * 8 + tg * 2;
                int c1 = c0 + 1;
                bool v00 = (c0 <= i0), v01 = (c1 <= i0), v10 = (c0 <= i1), v11 = (c1 <= i1);
                if (mode == 0) {
                    v00 = v00 && (i0 - c0 <= WSZ_);
                    v01 = v01 && (i0 - c1 <= WSZ_);
                    v10 = v10 && (i1 - c0 <= WSZ_);
                    v11 = v11 && (i1 - c1 <= WSZ_);
                }
                S[nt][0] = v00 ? S[nt][0] * 0.125f : -1e30f;
                S[nt][1] = v01 ? S[nt][1] * 0.125f : -1e30f;
                S[nt][2] = v10 ? S[nt][2] * 0.125f : -1e30f;
                S[nt][3] = v11 ? S[nt][3] * 0.125f : -1e30f;
            }

            float mx0 = -1e30f, mx1 = -1e30f;
            for (int nt = 0; nt < ntmax; nt++) {
                mx0 = fmaxf(mx0, fmaxf(S[nt][0], S[nt][1]));
                mx1 = fmaxf(mx1, fmaxf(S[nt][2], S[nt][3]));
            }
            mx0 = fmaxf(mx0, __shfl_xor_sync(0xffffffffu, mx0, 1));
            mx0 = fmaxf(mx0, __shfl_xor_sync(0xffffffffu, mx0, 2));
            mx1 = fmaxf(mx1, __shfl_xor_sync(0xffffffffu, mx1, 1));
            mx1 = fmaxf(mx1, __shfl_xor_sync(0xffffffffu, mx1, 2));

            float mn0 = fmaxf(m0, mx0), mn1 = fmaxf(m1, mx1);
            float sc0 = __expf(m0 - mn0), sc1 = __expf(m1 - mn1);
            m0 = mn0; m1 = mn1;

            float la0 = 0.f, la1 = 0.f;
            for (int nt = 0; nt < ntmax; nt++) {
                S[nt][0] = __expf(S[nt][0] - mn0);
                S[nt][1] = __expf(S[nt][1] - mn0);
                S[nt][2] = __expf(S[nt][2] - mn1);
                S[nt][3] = __expf(S[nt][3] - mn1);
                la0 += S[nt][0] + S[nt][1];
                la1 += S[nt][2] + S[nt][3];
            }
            la0 += __shfl_xor_sync(0xffffffffu, la0, 1);
            la0 += __shfl_xor_sync(0xffffffffu, la0, 2);
            la1 += __shfl_xor_sync(0xffffffffu, la1, 1);
            la1 += __shfl_xor_sync(0xffffffffu, la1, 2);
            l0 = l0 * sc0 + la0;
            l1 = l1 * sc1 + la1;

#pragma unroll
            for (int nt = 0; nt < 8; nt++) {
                O[nt][0] *= sc0; O[nt][1] *= sc0;
                O[nt][2] *= sc1; O[nt][3] *= sc1;
            }

            for (int kk = 0; kk < ntmax / 2; kk++) {
                u32 ph[4], pl[4];
                ph[0] = pack_hi2(S[2*kk][0],   S[2*kk][1]);
                pl[0] = pack_lo2(S[2*kk][0],   S[2*kk][1]);
                ph[1] = pack_hi2(S[2*kk][2],   S[2*kk][3]);
                pl[1] = pack_lo2(S[2*kk][2],   S[2*kk][3]);
                ph[2] = pack_hi2(S[2*kk+1][0], S[2*kk+1][1]);
                pl[2] = pack_lo2(S[2*kk+1][0], S[2*kk+1][1]);
                ph[3] = pack_hi2(S[2*kk+1][2], S[2*kk+1][3]);
                pl[3] = pack_lo2(S[2*kk+1][2], S[2*kk+1][3]);
#pragma unroll
                for (int ntp = 0; ntp < 4; ntp++) {
                    int krow = kk * 16 + (lane & 7) + (lane & 8);
                    int ncol = ntp * 16 + ((lane >> 4) << 3);
                    u32 vh2[4], vl2[4];
                    ldsm_x4_t(vh2, smem_u32(&sVh[krow][ncol]));
                    ldsm_x4_t(vl2, smem_u32(&sVl[krow][ncol]));
#pragma unroll
                    for (int t = 0; t < 2; t++)
                        mma16816(O[ntp * 2 + t], ph, &vh2[t * 2]);
#pragma unroll
                    for (int t = 0; t < 2; t++)
                        mma16816(O[ntp * 2 + t], ph, &vl2[t * 2]);
#pragma unroll
                    for (int t = 0; t < 2; t++)
                        mma16816(O[ntp * 2 + t], pl, &vh2[t * 2]);
                }
            }
            __syncthreads();
        }

        float g0 = g_gates[(b * T_ + i0) * 3 + mode];
        float g1 = g_gates[(b * T_ + i1) * 3 + mode];
        float inv0 = g0 / l0, inv1 = g1 / l1;
#pragma unroll
        for (int nt = 0; nt < 8; nt++) {
            Of[nt][0] += O[nt][0] * inv0;
            Of[nt][1] += O[nt][1] * inv0;
            Of[nt][2] += O[nt][2] * inv1;
            Of[nt][3] += O[nt][3] * inv1;
        }
    }

    float* o0 = g_attn + ((size_t)(b * T_ + i0)) * C_ + h * HS_;
    float* o1 = g_attn + ((size_t)(b * T_ + i1)) * C_ + h * HS_;
#pragma unroll
    for (int nt = 0; nt < 8; nt++) {
        int c = nt * 8 + tg * 2;
        o0[c]     = Of[nt][0];
        o0[c + 1] = Of[nt][1];
        o1[c]     = Of[nt][2];
        o1[c + 1] = Of[nt][3];
    }
}

// ---------------- host launch ----------------
extern "C" void kernel_launch(void* const* d_in, const int* in_sizes, int n_in,
                              void* d_out, int out_size)
{
    const float* x  = (const float*)d_in[0];
    const float* Wq = (const float*)d_in[1];
    const float* bq = (const float*)d_in[2];
    const float* Wk = (const float*)d_in[3];
    const float* bk = (const float*)d_in[4];
    const float* Wv = (const float*)d_in[5];
    const float* bv = (const float*)d_in[6];
    const float* Wo = (const float*)d_in[7];
    const float* bo = (const float*)d_in[8];
    const float* Wg = (const float*)d_in[9];
    const float* bg = (const float*)d_in[10];
    float* out = (float*)d_out;

    float *qp, *kp, *vp, *ap;
    cudaGetSymbolAddress((void**)&qp, g_q);
    cudaGetSymbolAddress((void**)&kp, g_k);
    cudaGetSymbolAddress((void**)&vp, g_v);
    cudaGetSymbolAddress((void**)&ap, g_attn);
    __nv_bfloat16 *xh, *xl, *ah, *al, *wh, *wl;
    cudaGetSymbolAddress((void**)&xh, g_xh);
    cudaGetSymbolAddress((void**)&xl, g_xl);
    cudaGetSymbolAddress((void**)&ah, g_ah);
    cudaGetSymbolAddress((void**)&al, g_al);
    cudaGetSymbolAddress((void**)&wh, g_wh);
    cudaGetSymbolAddress((void**)&wl, g_wl);

    cudaFuncSetAttribute(gemm_bf16x3_kernel, cudaFuncAttributeMaxDynamicSharedMemorySize, GEMM_SMEM);

    const int nX4 = (M_ * C_) / 4;
    const int nW4 = (C_ * C_) / 4;

    dim3 ggrid(C_ / 128, M_ / 128);

    split_kernel<<<(nX4 + 255) / 256, 256>>>(x, xh, xl, nX4);

    split_kernel<<<(nW4 + 255) / 256, 256>>>(Wq, wh, wl, nW4);
    gemm_bf16x3_kernel<<<ggrid, 256, GEMM_SMEM>>>(xh, xl, wh, wl, bq, qp, M_, C_, C_);
    split_kernel<<<(nW4 + 255) / 256, 256>>>(Wk, wh, wl, nW4);
    gemm_bf16x3_kernel<<<ggrid, 256, GEMM_SMEM>>>(xh, xl, wh, wl, bk, kp, M_, C_, C_);
    split_kernel<<<(nW4 + 255) / 256, 256>>>(Wv, wh, wl, nW4);
    gemm_bf16x3_kernel<<<ggrid, 256, GEMM_SMEM>>>(xh, xl, wh, wl, bv, vp, M_, C_, C_);

    gates_kernel<<<(B_ * T_ * 32) / 256, 256>>>(x, Wg, bg);
    blockmean_kernel<<<(B_ * H_ * NB_ * HS_) / 256, 256>>>();
    qbar1_kernel<<<B_ * H_ * 8, 256>>>();
    qbar2_kernel<<<B_ * H_, 64>>>();
    topk_kernel<<<B_ * H_, 32>>>();
    gather_kernel<<<(B_ * H_ * NSEL_ * BLK_ * HS_) / 256, 256>>>();

    dim3 agrid(T_ / 64, H_, B_);
    tc_attn_all<<<agrid, 128>>>();

    split_kernel<<<(nX4 + 255) / 256, 256>>>(ap, ah, al, nX4);
    split_kernel<<<(nW4 + 255) / 256, 256>>>(Wo, wh, wl, nW4);
    gemm_bf16x3_kernel<<<ggrid, 256, GEMM_SMEM>>>(ah, al, wh, wl, bo, out, M_, C_, C_);
}

// round 16
// speedup vs baseline: 1.0634x; 1.0634x over previous
#include <cuda_runtime.h>
#include <cuda_bf16.h>
#include <stdint.h>
#include <math.h>

typedef unsigned int u32;

#define B_  2
#define T_  2048
#define C_  1024
#define H_  16
#define HS_ 64
#define NB_ 32
#define BLK_ 64
#define NSEL_ 8
#define WSZ_ 128
#define M_  (B_*T_)

// ---------------- device scratch ----------------
__device__ float g_q[B_*T_*C_];
__device__ float g_k[B_*T_*C_];
__device__ float g_v[B_*T_*C_];
__device__ float g_attn[B_*T_*C_];
__device__ float g_gates[B_*T_*3];
__device__ float g_krep[B_*H_*NB_*HS_];
__device__ float g_vcmp[B_*H_*NB_*HS_];
__device__ float g_qbar[B_*H_*HS_];
__device__ float g_qbar_part[B_*H_*8*HS_];
__device__ int   g_topidx[B_*H_*NSEL_];
__device__ float g_selk[B_*H_*NSEL_*BLK_*HS_];
__device__ float g_selv[B_*H_*NSEL_*BLK_*HS_];

__device__ __nv_bfloat16 g_xh[M_*C_];
__device__ __nv_bfloat16 g_xl[M_*C_];
__device__ __nv_bfloat16 g_ah[M_*C_];
__device__ __nv_bfloat16 g_al[M_*C_];
__device__ __nv_bfloat16 g_wh[C_*C_];
__device__ __nv_bfloat16 g_wl[C_*C_];

// ---------------- helpers ----------------
__device__ __forceinline__ u32 smem_u32(const void* p) {
    u32 a;
    asm("{ .reg .u64 t; cvta.to.shared.u64 t, %1; cvt.u32.u64 %0, t; }" : "=r"(a) : "l"(p));
    return a;
}
__device__ __forceinline__ void cp16s(u32 saddr, const void* g) {
    asm volatile("cp.async.cg.shared.global [%0], [%1], 16;\n" :: "r"(saddr), "l"(g));
}
__device__ __forceinline__ void ldsm_x4(u32* r, u32 addr) {
    asm volatile("ldmatrix.sync.aligned.m8n8.x4.shared.b16 {%0,%1,%2,%3}, [%4];"
        : "=r"(r[0]), "=r"(r[1]), "=r"(r[2]), "=r"(r[3]) : "r"(addr));
}
__device__ __forceinline__ void ldsm_x4_t(u32* r, u32 addr) {
    asm volatile("ldmatrix.sync.aligned.m8n8.x4.trans.shared.b16 {%0,%1,%2,%3}, [%4];"
        : "=r"(r[0]), "=r"(r[1]), "=r"(r[2]), "=r"(r[3]) : "r"(addr));
}
__device__ __forceinline__ void mma16816(float* d, const u32* a, const u32* b) {
    asm volatile(
        "mma.sync.aligned.m16n8k16.row.col.f32.bf16.bf16.f32 "
        "{%0,%1,%2,%3},{%4,%5,%6,%7},{%8,%9},{%0,%1,%2,%3};"
        : "+f"(d[0]), "+f"(d[1]), "+f"(d[2]), "+f"(d[3])
        : "r"(a[0]), "r"(a[1]), "r"(a[2]), "r"(a[3]), "r"(b[0]), "r"(b[1]));
}
__device__ __forceinline__ u32 pack_hi2(float a, float b) {
    __nv_bfloat162 t = __halves2bfloat162(__float2bfloat16(a), __float2bfloat16(b));
    return *(u32*)&t;
}
__device__ __forceinline__ u32 pack_lo2(float a, float b) {
    __nv_bfloat16 ha = __float2bfloat16(a), hb = __float2bfloat16(b);
    __nv_bfloat162 t = __halves2bfloat162(
        __float2bfloat16(a - __bfloat162float(ha)),
        __float2bfloat16(b - __bfloat162float(hb)));
    return *(u32*)&t;
}

// ---------------- fp32 -> bf16 hi/lo split ----------------
__global__ void split_kernel(const float* __restrict__ src,
                             __nv_bfloat16* __restrict__ hi,
                             __nv_bfloat16* __restrict__ lo, int n4)
{
    int i = blockIdx.x * blockDim.x + threadIdx.x;
    if (i >= n4) return;
    float4 v = ((const float4*)src)[i];
    __nv_bfloat16 h0 = __float2bfloat16(v.x);
    __nv_bfloat16 h1 = __float2bfloat16(v.y);
    __nv_bfloat16 h2 = __float2bfloat16(v.z);
    __nv_bfloat16 h3 = __float2bfloat16(v.w);
    __nv_bfloat16 l0 = __float2bfloat16(v.x - __bfloat162float(h0));
    __nv_bfloat16 l1 = __float2bfloat16(v.y - __bfloat162float(h1));
    __nv_bfloat16 l2 = __float2bfloat16(v.z - __bfloat162float(h2));
    __nv_bfloat16 l3 = __float2bfloat16(v.w - __bfloat162float(h3));
    __nv_bfloat162* hp = (__nv_bfloat162*)hi;
    __nv_bfloat162* lp = (__nv_bfloat162*)lo;
    hp[i*2]   = __halves2bfloat162(h0, h1);
    hp[i*2+1] = __halves2bfloat162(h2, h3);
    lp[i*2]   = __halves2bfloat162(l0, l1);
    lp[i*2+1] = __halves2bfloat162(l2, l3);
}

// ---------------- GEMM: BK=32, 2-stage cp.async, term-major MMAs (R13-proven) ----------------
#define BK3 32
#define A_ROW 40
#define B_ROW 136
#define A_STG (128 * A_ROW)
#define B_STG (32 * B_ROW)
#define GEMM_SMEM ((4 * A_STG + 4 * B_STG) * 2)   // 75776 bytes

__global__ void __launch_bounds__(256) gemm_bf16x3_kernel(
    const __nv_bfloat16* __restrict__ Ah, const __nv_bfloat16* __restrict__ Al,
    const __nv_bfloat16* __restrict__ Bh, const __nv_bfloat16* __restrict__ Bl,
    const float* __restrict__ bias, float* __restrict__ C,
    int M, int N, int K)
{
    extern __shared__ __align__(16) __nv_bfloat16 sm[];
    __nv_bfloat16* sAh = sm;
    __nv_bfloat16* sAl = sm + 2 * A_STG;
    __nv_bfloat16* sBh = sm + 4 * A_STG;
    __nv_bfloat16* sBl = sm + 4 * A_STG + 2 * B_STG;

    int tid = threadIdx.x;
    int lane = tid & 31, warp = tid >> 5;
    int wm = warp >> 1, wn = warp & 1;
    int bm0 = blockIdx.y * 128, bn0 = blockIdx.x * 128;

    int ar0 = tid >> 1,  ac0 = (tid & 1) << 3;
    int ac1 = ac0 + 16;
    int br0 = tid >> 4,  bc0 = (tid & 15) << 3;
    int br1 = br0 + 16;
    const __nv_bfloat16* pAh0 = Ah + (size_t)(bm0 + ar0) * K + ac0;
    const __nv_bfloat16* pAl0 = Al + (size_t)(bm0 + ar0) * K + ac0;
    const __nv_bfloat16* pAh1 = Ah + (size_t)(bm0 + ar0) * K + ac1;
    const __nv_bfloat16* pAl1 = Al + (size_t)(bm0 + ar0) * K + ac1;
    const __nv_bfloat16* pBh0 = Bh + (size_t)br0 * N + bn0 + bc0;
    const __nv_bfloat16* pBl0 = Bl + (size_t)br0 * N + bn0 + bc0;
    const __nv_bfloat16* pBh1 = Bh + (size_t)br1 * N + bn0 + bc0;
    const __nv_bfloat16* pBl1 = Bl + (size_t)br1 * N + bn0 + bc0;
    const u32 a0o = (u32)(ar0 * A_ROW + ac0) * 2;
    const u32 a1o = (u32)(ar0 * A_ROW + ac1) * 2;
    const u32 b0o = (u32)(br0 * B_ROW + bc0) * 2;
    const u32 b1o = (u32)(br1 * B_ROW + bc0) * 2;
    const u32 sAhB = smem_u32(sAh), sAlB = smem_u32(sAl);
    const u32 sBhB = smem_u32(sBh), sBlB = smem_u32(sBl);

    float acc[2][8][4];
#pragma unroll
    for (int mt = 0; mt < 2; mt++)
#pragma unroll
        for (int nt = 0; nt < 8; nt++)
#pragma unroll
            for (int r = 0; r < 4; r++) acc[mt][nt][r] = 0.f;

    const int NK = K / BK3;

#define LOADK(stage, kc) do { \
    u32 as = (u32)(stage) * (A_STG * 2), bs = (u32)(stage) * (B_STG * 2); \
    int ko = (kc) * BK3; \
    cp16s(sAhB + as + a0o, pAh0 + ko); \
    cp16s(sAhB + as + a1o, pAh1 + ko); \
    cp16s(sAlB + as + a0o, pAl0 + ko); \
    cp16s(sAlB + as + a1o, pAl1 + ko); \
    cp16s(sBhB + bs + b0o, pBh0 + (size_t)ko * N); \
    cp16s(sBhB + bs + b1o, pBh1 + (size_t)ko * N); \
    cp16s(sBlB + bs + b0o, pBl0 + (size_t)ko * N); \
    cp16s(sBlB + bs + b1o, pBl1 + (size_t)ko * N); \
    asm volatile("cp.async.commit_group;\n" ::: "memory"); \
} while (0)

    LOADK(0, 0);

    for (int k = 0; k < NK; k++) {
        int cur = k & 1;
        if (k + 1 < NK) {
            LOADK(1 - cur, k + 1);
            asm volatile("cp.async.wait_group 1;\n" ::: "memory");
        } else {
            asm volatile("cp.async.wait_group 0;\n" ::: "memory");
        }
        __syncthreads();

        u32 aBase = (u32)cur * (A_STG * 2);
        u32 bBase = (u32)cur * (B_STG * 2);
#pragma unroll
        for (int ks = 0; ks < 2; ks++) {
            u32 ah[2][4], al[2][4];
#pragma unroll
            for (int mt = 0; mt < 2; mt++) {
                int row = wm * 32 + mt * 16 + (lane & 15);
                int col = ks * 16 + ((lane >> 4) << 3);
                u32 o = (u32)(row * A_ROW + col) * 2;
                ldsm_x4(ah[mt], sAhB + aBase + o);
                ldsm_x4(al[mt], sAlB + aBase + o);
            }
#pragma unroll
            for (int np = 0; np < 4; np++) {
                int krow = ks * 16 + (lane & 7) + (lane & 8);
                int ncol = wn * 64 + np * 16 + ((lane >> 4) << 3);
                u32 o = (u32)(krow * B_ROW + ncol) * 2;
                u32 bh[4], bl[4];
                ldsm_x4_t(bh, sBhB + bBase + o);
                ldsm_x4_t(bl, sBlB + bBase + o);
#pragma unroll
                for (int mt = 0; mt < 2; mt++)
#pragma unroll
                    for (int t = 0; t < 2; t++)
                        mma16816(acc[mt][np * 2 + t], ah[mt], &bh[t * 2]);
#pragma unroll
                for (int mt = 0; mt < 2; mt++)
#pragma unroll
                    for (int t = 0; t < 2; t++)
                        mma16816(acc[mt][np * 2 + t], ah[mt], &bl[t * 2]);
#pragma unroll
                for (int mt = 0; mt < 2; mt++)
#pragma unroll
                    for (int t = 0; t < 2; t++)
                        mma16816(acc[mt][np * 2 + t], al[mt], &bh[t * 2]);
            }
        }
        __syncthreads();
    }
#undef LOADK

    int grp = lane >> 2, tg = lane & 3;
#pragma unroll
    for (int mt = 0; mt < 2; mt++) {
#pragma unroll
        for (int nt = 0; nt < 8; nt++) {
            int row = bm0 + wm * 32 + mt * 16 + grp;
            int col = bn0 + wn * 64 + nt * 8 + tg * 2;
            float b0 = bias[col], b1 = bias[col + 1];
            float* c0 = C + (size_t)row * N + col;
            float* c1 = C + (size_t)(row + 8) * N + col;
            c0[0] = acc[mt][nt][0] + b0;
            c0[1] = acc[mt][nt][1] + b1;
            c1[0] = acc[mt][nt][2] + b0;
            c1[1] = acc[mt][nt][3] + b1;
        }
    }
}

// ---------------- gates ----------------
__global__ void gates_kernel(const float* __restrict__ x,
                             const float* __restrict__ Wg,
                             const float* __restrict__ bg)
{
    int gidx = blockIdx.x * blockDim.x + threadIdx.x;
    int w = gidx >> 5, lane = gidx & 31;
    if (w >= B_ * T_) return;
    const float* xr = x + (size_t)w * C_;
    float s0 = 0, s1 = 0, s2 = 0;
    for (int c = lane; c < C_; c += 32) {
        float xv = xr[c];
        s0 += xv * Wg[c * 3 + 0];
        s1 += xv * Wg[c * 3 + 1];
        s2 += xv * Wg[c * 3 + 2];
    }
#pragma unroll
    for (int o = 16; o; o >>= 1) {
        s0 += __shfl_xor_sync(0xffffffffu, s0, o);
        s1 += __shfl_xor_sync(0xffffffffu, s1, o);
        s2 += __shfl_xor_sync(0xffffffffu, s2, o);
    }
    if (lane == 0) {
        s0 += bg[0]; s1 += bg[1]; s2 += bg[2];
        float mx = fmaxf(s0, fmaxf(s1, s2));
        float e0 = __expf(s0 - mx), e1 = __expf(s1 - mx), e2 = __expf(s2 - mx);
        float inv = 1.f / (e0 + e1 + e2);
        g_gates[w * 3 + 0] = e0 * inv;
        g_gates[w * 3 + 1] = e1 * inv;
        g_gates[w * 3 + 2] = e2 * inv;
    }
}

// ---------------- per-block mean of K and V ----------------
__global__ void blockmean_kernel()
{
    int idx = blockIdx.x * blockDim.x + threadIdx.x;
    if (idx >= B_ * H_ * NB_ * HS_) return;
    int d = idx & 63;
    int n = (idx >> 6) & 31;
    int h = (idx >> 11) & 15;
    int b = idx >> 15;
    const float* kp = g_k + ((size_t)(b * T_ + n * BLK_)) * C_ + h * HS_ + d;
    const float* vp = g_v + ((size_t)(b * T_ + n * BLK_)) * C_ + h * HS_ + d;
    float sk = 0.f, sv = 0.f;
    for (int j = 0; j < BLK_; j++) {
        sk += kp[(size_t)j * C_];
        sv += vp[(size_t)j * C_];
    }
    g_krep[idx] = sk * (1.f / BLK_);
    g_vcmp[idx] = sv * (1.f / BLK_);
}

// ---------------- qbar phase 1 ----------------
__global__ void qbar1_kernel()
{
    int bh = blockIdx.x >> 3, chunk = blockIdx.x & 7;
    int b = bh >> 4, h = bh & 15;
    int warp = threadIdx.x >> 5, lane = threadIdx.x & 31;
    float a0 = 0.f, a1 = 0.f;
    int t0 = chunk * 256;
    for (int t = t0 + warp; t < t0 + 256; t += 8) {
        const float* qr = g_q + ((size_t)(b * T_ + t)) * C_ + h * HS_;
        float x0 = qr[lane], x1 = qr[lane + 32];
        float ss = x0 * x0 + x1 * x1;
#pragma unroll
        for (int o = 16; o; o >>= 1) ss += __shfl_xor_sync(0xffffffffu, ss, o);
        float inv = 1.f / fmaxf(sqrtf(ss), 1e-8f);
        a0 += x0 * inv;
        a1 += x1 * inv;
    }
    __shared__ float acc[64];
    if (threadIdx.x < 64) acc[threadIdx.x] = 0.f;
    __syncthreads();
    atomicAdd(&acc[lane], a0);
    atomicAdd(&acc[lane + 32], a1);
    __syncthreads();
    if (threadIdx.x < 64)
        g_qbar_part[(size_t)blockIdx.x * 64 + threadIdx.x] = acc[threadIdx.x];
}

// ---------------- qbar phase 2 ----------------
__global__ void qbar2_kernel()
{
    int bh = blockIdx.x, d = threadIdx.x;
    float s = 0.f;
#pragma unroll
    for (int c = 0; c < 8; c++)
        s += g_qbar_part[((size_t)bh * 8 + c) * 64 + d];
    g_qbar[bh * 64 + d] = s;
}

// ---------------- top-8 ----------------
__global__ void topk_kernel()
{
    int bh = blockIdx.x;
    int n = threadIdx.x;
    const float* kr = g_krep + ((size_t)bh * NB_ + n) * HS_;
    const float* qb = g_qbar + (size_t)bh * HS_;
    float dot = 0.f, ss = 0.f;
    for (int d = 0; d < HS_; d++) {
        float kv = kr[d];
        dot += kv * qb[d];
        ss += kv * kv;
    }
    float score = dot / fmaxf(sqrtf(ss), 1e-8f);
    __shared__ float sc[NB_];
    sc[n] = score;
    __syncthreads();
    if (n == 0) {
        bool used[NB_];
        for (int m = 0; m < NB_; m++) used[m] = false;
        for (int s = 0; s < NSEL_; s++) {
            float best = -1e30f; int bi = 0;
            for (int m = 0; m < NB_; m++)
                if (!used[m] && sc[m] > best) { best = sc[m]; bi = m; }
            used[bi] = true;
            g_topidx[bh * NSEL_ + s] = bi;
        }
    }
}

// ---------------- gather selected K/V ----------------
__global__ void gather_kernel()
{
    int idx = blockIdx.x * blockDim.x + threadIdx.x;
    if (idx >= B_ * H_ * NSEL_ * BLK_ * HS_) return;
    int d = idx & 63;
    int s = (idx >> 6) & 511;
    int h = (idx >> 15) & 15;
    int b = idx >> 19;
    int blk = g_topidx[(b * H_ + h) * NSEL_ + (s >> 6)];
    int row = blk * BLK_ + (s & 63);
    size_t src = ((size_t)(b * T_ + row)) * C_ + h * HS_ + d;
    g_selk[idx] = g_k[src];
    g_selv[idx] = g_v[src];
}

// ---------------- merged tensor-core attention: 128 queries/block, 8 warps ----------------
__global__ void __launch_bounds__(256) tc_attn_all()
{
    const int qt = blockIdx.x;             // 128-query tile
    const int h = blockIdx.y, b = blockIdx.z;
    const int q0 = qt * 128;
    const int lane = threadIdx.x & 31, warp = threadIdx.x >> 5;   // 8 warps
    const int g = lane >> 2, tg = lane & 3;
    const int i0 = q0 + warp * 16 + g;
    const int i1 = i0 + 8;

    __shared__ __align__(16) __nv_bfloat16 sKh[64][72];
    __shared__ __align__(16) __nv_bfloat16 sKl[64][72];
    __shared__ __align__(16) __nv_bfloat16 sVh[64][72];
    __shared__ __align__(16) __nv_bfloat16 sVl[64][72];

    u32 qh[4][4], ql[4][4];
    {
        const float* qr0 = g_q + ((size_t)(b * T_ + i0)) * C_ + h * HS_;
        const float* qr1 = g_q + ((size_t)(b * T_ + i1)) * C_ + h * HS_;
#pragma unroll
        for (int kk = 0; kk < 4; kk++) {
            int c = kk * 16 + tg * 2;
            qh[kk][0] = pack_hi2(qr0[c], qr0[c + 1]);
            ql[kk][0] = pack_lo2(qr0[c], qr0[c + 1]);
            qh[kk][1] = pack_hi2(qr1[c], qr1[c + 1]);
            ql[kk][1] = pack_lo2(qr1[c], qr1[c + 1]);
            qh[kk][2] = pack_hi2(qr0[c + 8], qr0[c + 9]);
            ql[kk][2] = pack_lo2(qr0[c + 8], qr0[c + 9]);
            qh[kk][3] = pack_hi2(qr1[c + 8], qr1[c + 9]);
            ql[kk][3] = pack_lo2(qr1[c + 8], qr1[c + 9]);
        }
    }

    float Of[8][4];
#pragma unroll
    for (int nt = 0; nt < 8; nt++)
#pragma unroll
        for (int r = 0; r < 4; r++) Of[nt][r] = 0.f;

    for (int mode = 0; mode < 3; mode++) {
        float O[8][4];
#pragma unroll
        for (int nt = 0; nt < 8; nt++)
#pragma unroll
            for (int r = 0; r < 4; r++) O[nt][r] = 0.f;
        float m0 = -1e30f, m1 = -1e30f, l0 = 0.f, l1 = 0.f;

        int kt0, kt1, krows, ntmax;
        if (mode == 0)      { kt0 = (qt >= 1 ? 2 * qt - 2 : 0); kt1 = 2 * qt + 1; krows = 64; ntmax = 8; }
        else if (mode == 1) { kt0 = 0; int m1i = 2 * qt + 1; kt1 = (m1i < 7 ? m1i : 7); krows = 64; ntmax = 8; }
        else                { kt0 = 0; kt1 = 0; krows = 32; ntmax = 4; }

        for (int kt = kt0; kt <= kt1; kt++) {
            const float* ksrc; const float* vsrc; int kstride;
            if (mode == 0) {
                ksrc = g_k + ((size_t)(b * T_ + kt * 64)) * C_ + h * HS_;
                vsrc = g_v + ((size_t)(b * T_ + kt * 64)) * C_ + h * HS_;
                kstride = C_;
            } else if (mode == 1) {
                ksrc = g_selk + ((size_t)((b * H_ + h) * 512 + kt * 64)) * HS_;
                vsrc = g_selv + ((size_t)((b * H_ + h) * 512 + kt * 64)) * HS_;
                kstride = HS_;
            } else {
                ksrc = g_krep + ((size_t)(b * H_ + h) * NB_) * HS_;
                vsrc = g_vcmp + ((size_t)(b * H_ + h) * NB_) * HS_;
                kstride = HS_;
            }
            for (int idx = threadIdx.x; idx < krows * 16; idx += 256) {
                int r = idx >> 4, c = (idx & 15) * 4;
                float4 kv = *(const float4*)(ksrc + (size_t)r * kstride + c);
                float4 vv = *(const float4*)(vsrc + (size_t)r * kstride + c);
                __nv_bfloat16 h0 = __float2bfloat16(kv.x), h1 = __float2bfloat16(kv.y);
                __nv_bfloat16 h2 = __float2bfloat16(kv.z), h3 = __float2bfloat16(kv.w);
                sKh[r][c] = h0; sKh[r][c+1] = h1; sKh[r][c+2] = h2; sKh[r][c+3] = h3;
                sKl[r][c]   = __float2bfloat16(kv.x - __bfloat162float(h0));
                sKl[r][c+1] = __float2bfloat16(kv.y - __bfloat162float(h1));
                sKl[r][c+2] = __float2bfloat16(kv.z - __bfloat162float(h2));
                sKl[r][c+3] = __float2bfloat16(kv.w - __bfloat162float(h3));
                h0 = __float2bfloat16(vv.x); h1 = __float2bfloat16(vv.y);
                h2 = __float2bfloat16(vv.z); h3 = __float2bfloat16(vv.w);
                sVh[r][c] = h0; sVh[r][c+1] = h1; sVh[r][c+2] = h2; sVh[r][c+3] = h3;
                sVl[r][c]   = __float2bfloat16(vv.x - __bfloat162float(h0));
                sVl[r][c+1] = __float2bfloat16(vv.y - __bfloat162float(h1));
                sVl[r][c+2] = __float2bfloat16(vv.z - __bfloat162float(h2));
                sVl[r][c+3] = __float2bfloat16(vv.w - __bfloat162float(h3));
            }
            __syncthreads();

            float S[8][4];
#pragma unroll
            for (int nt = 0; nt < 8; nt++)
#pragma unroll
                for (int r = 0; r < 4; r++) S[nt][r] = 0.f;

#pragma unroll
            for (int kk = 0; kk < 4; kk++) {
                for (int ntp = 0; ntp < ntmax / 2; ntp++) {
                    int row = ntp * 16 + ((lane >> 4) << 3) + (lane & 7);
                    int col = kk * 16 + (((lane >> 3) & 1) << 3);
                    u32 kh2[4], kl2[4];
                    ldsm_x4(kh2, smem_u32(&sKh[row][col]));
                    ldsm_x4(kl2, smem_u32(&sKl[row][col]));
#pragma unroll
                    for (int t = 0; t < 2; t++)
                        mma16816(S[ntp * 2 + t], qh[kk], &kh2[t * 2]);
#pragma unroll
                    for (int t = 0; t < 2; t++)
                        mma16816(S[ntp * 2 + t], qh[kk], &kl2[t * 2]);
#pragma unroll
                    for (int t = 0; t < 2; t++)
                        mma16816(S[ntp * 2 + t], ql[kk], &kh2[t * 2]);
                }
            }

            const int tilebase = kt * 64;
            for (int nt = 0; nt < ntmax; nt++) {
                int c0 = tilebase + nt * 8 + tg * 2;
                int c1 = c0 + 1;
                bool v00 = (c0 <= i0), v01 = (c1 <= i0), v10 = (c0 <= i1), v11 = (c1 <= i1);
                if (mode == 0) {
                    v00 = v00 && (i0 - c0 <= WSZ_);
                    v01 = v01 && (i0 - c1 <= WSZ_);
                    v10 = v10 && (i1 - c0 <= WSZ_);
                    v11 = v11 && (i1 - c1 <= WSZ_);
                }
                S[nt][0] = v00 ? S[nt][0] * 0.125f : -1e30f;
                S[nt][1] = v01 ? S[nt][1] * 0.125f : -1e30f;
                S[nt][2] = v10 ? S[nt][2] * 0.125f : -1e30f;
                S[nt][3] = v11 ? S[nt][3] * 0.125f : -1e30f;
            }

            float mx0 = -1e30f, mx1 = -1e30f;
            for (int nt = 0; nt < ntmax; nt++) {
                mx0 = fmaxf(mx0, fmaxf(S[nt][0], S[nt][1]));
                mx1 = fmaxf(mx1, fmaxf(S[nt][2], S[nt][3]));
            }
            mx0 = fmaxf(mx0, __shfl_xor_sync(0xffffffffu, mx0, 1));
            mx0 = fmaxf(mx0, __shfl_xor_sync(0xffffffffu, mx0, 2));
            mx1 = fmaxf(mx1, __shfl_xor_sync(0xffffffffu, mx1, 1));
            mx1 = fmaxf(mx1, __shfl_xor_sync(0xffffffffu, mx1, 2));

            float mn0 = fmaxf(m0, mx0), mn1 = fmaxf(m1, mx1);
            float sc0 = __expf(m0 - mn0), sc1 = __expf(m1 - mn1);
            m0 = mn0; m1 = mn1;

            float la0 = 0.f, la1 = 0.f;
            for (int nt = 0; nt < ntmax; nt++) {
                S[nt][0] = __expf(S[nt][0] - mn0);
                S[nt][1] = __expf(S[nt][1] - mn0);
                S[nt][2] = __expf(S[nt][2] - mn1);
                S[nt][3] = __expf(S[nt][3] - mn1);
                la0 += S[nt][0] + S[nt][1];
                la1 += S[nt][2] + S[nt][3];
            }
            la0 += __shfl_xor_sync(0xffffffffu, la0, 1);
            la0 += __shfl_xor_sync(0xffffffffu, la0, 2);
            la1 += __shfl_xor_sync(0xffffffffu, la1, 1);
            la1 += __shfl_xor_sync(0xffffffffu, la1, 2);
            l0 = l0 * sc0 + la0;
            l1 = l1 * sc1 + la1;

#pragma unroll
            for (int nt = 0; nt < 8; nt++) {
                O[nt][0] *= sc0; O[nt][1] *= sc0;
                O[nt][2] *= sc1; O[nt][3] *= sc1;
            }

            for (int kk = 0; kk < ntmax / 2; kk++) {
                u32 ph[4], pl[4];
                ph[0] = pack_hi2(S[2*kk][0],   S[2*kk][1]);
                pl[0] = pack_lo2(S[2*kk][0],   S[2*kk][1]);
                ph[1] = pack_hi2(S[2*kk][2],   S[2*kk][3]);
                pl[1] = pack_lo2(S[2*kk][2],   S[2*kk][3]);
                ph[2] = pack_hi2(S[2*kk+1][0], S[2*kk+1][1]);
                pl[2] = pack_lo2(S[2*kk+1][0], S[2*kk+1][1]);
                ph[3] = pack_hi2(S[2*kk+1][2], S[2*kk+1][3]);
                pl[3] = pack_lo2(S[2*kk+1][2], S[2*kk+1][3]);
#pragma unroll
                for (int ntp = 0; ntp < 4; ntp++) {
                    int krow = kk * 16 + (lane & 7) + (lane & 8);
                    int ncol = ntp * 16 + ((lane >> 4) << 3);
                    u32 vh2[4], vl2[4];
                    ldsm_x4_t(vh2, smem_u32(&sVh[krow][ncol]));
                    ldsm_x4_t(vl2, smem_u32(&sVl[krow][ncol]));
#pragma unroll
                    for (int t = 0; t < 2; t++)
                        mma16816(O[ntp * 2 + t], ph, &vh2[t * 2]);
#pragma unroll
                    for (int t = 0; t < 2; t++)
                        mma16816(O[ntp * 2 + t], ph, &vl2[t * 2]);
#pragma unroll
                    for (int t = 0; t < 2; t++)
                        mma16816(O[ntp * 2 + t], pl, &vh2[t * 2]);
                }
            }
            __syncthreads();
        }

        float g0 = g_gates[(b * T_ + i0) * 3 + mode];
        float g1 = g_gates[(b * T_ + i1) * 3 + mode];
        float inv0 = g0 / l0, inv1 = g1 / l1;
#pragma unroll
        for (int nt = 0; nt < 8; nt++) {
            Of[nt][0] += O[nt][0] * inv0;
            Of[nt][1] += O[nt][1] * inv0;
            Of[nt][2] += O[nt][2] * inv1;
            Of[nt][3] += O[nt][3] * inv1;
        }
    }

    float* o0 = g_attn + ((size_t)(b * T_ + i0)) * C_ + h * HS_;
    float* o1 = g_attn + ((size_t)(b * T_ + i1)) * C_ + h * HS_;
#pragma unroll
    for (int nt = 0; nt < 8; nt++) {
        int c = nt * 8 + tg * 2;
        o0[c]     = Of[nt][0];
        o0[c + 1] = Of[nt][1];
        o1[c]     = Of[nt][2];
        o1[c + 1] = Of[nt][3];
    }
}

// ---------------- host launch ----------------
extern "C" void kernel_launch(void* const* d_in, const int* in_sizes, int n_in,
                              void* d_out, int out_size)
{
    const float* x  = (const float*)d_in[0];
    const float* Wq = (const float*)d_in[1];
    const float* bq = (const float*)d_in[2];
    const float* Wk = (const float*)d_in[3];
    const float* bk = (const float*)d_in[4];
    const float* Wv = (const float*)d_in[5];
    const float* bv = (const float*)d_in[6];
    const float* Wo = (const float*)d_in[7];
    const float* bo = (const float*)d_in[8];
    const float* Wg = (const float*)d_in[9];
    const float* bg = (const float*)d_in[10];
    float* out = (float*)d_out;

    float *qp, *kp, *vp, *ap;
    cudaGetSymbolAddress((void**)&qp, g_q);
    cudaGetSymbolAddress((void**)&kp, g_k);
    cudaGetSymbolAddress((void**)&vp, g_v);
    cudaGetSymbolAddress((void**)&ap, g_attn);
    __nv_bfloat16 *xh, *xl, *ah, *al, *wh, *wl;
    cudaGetSymbolAddress((void**)&xh, g_xh);
    cudaGetSymbolAddress((void**)&xl, g_xl);
    cudaGetSymbolAddress((void**)&ah, g_ah);
    cudaGetSymbolAddress((void**)&al, g_al);
    cudaGetSymbolAddress((void**)&wh, g_wh);
    cudaGetSymbolAddress((void**)&wl, g_wl);

    cudaFuncSetAttribute(gemm_bf16x3_kernel, cudaFuncAttributeMaxDynamicSharedMemorySize, GEMM_SMEM);

    const int nX4 = (M_ * C_) / 4;
    const int nW4 = (C_ * C_) / 4;

    dim3 ggrid(C_ / 128, M_ / 128);

    split_kernel<<<(nX4 + 255) / 256, 256>>>(x, xh, xl, nX4);

    split_kernel<<<(nW4 + 255) / 256, 256>>>(Wq, wh, wl, nW4);
    gemm_bf16x3_kernel<<<ggrid, 256, GEMM_SMEM>>>(xh, xl, wh, wl, bq, qp, M_, C_, C_);
    split_kernel<<<(nW4 + 255) / 256, 256>>>(Wk, wh, wl, nW4);
    gemm_bf16x3_kernel<<<ggrid, 256, GEMM_SMEM>>>(xh, xl, wh, wl, bk, kp, M_, C_, C_);
    split_kernel<<<(nW4 + 255) / 256, 256>>>(Wv, wh, wl, nW4);
    gemm_bf16x3_kernel<<<ggrid, 256, GEMM_SMEM>>>(xh, xl, wh, wl, bv, vp, M_, C_, C_);

    gates_kernel<<<(B_ * T_ * 32) / 256, 256>>>(x, Wg, bg);
    blockmean_kernel<<<(B_ * H_ * NB_ * HS_) / 256, 256>>>();
    qbar1_kernel<<<B_ * H_ * 8, 256>>>();
    qbar2_kernel<<<B_ * H_, 64>>>();
    topk_kernel<<<B_ * H_, 32>>>();
    gather_kernel<<<(B_ * H_ * NSEL_ * BLK_ * HS_) / 256, 256>>>();

    dim3 agrid(T_ / 128, H_, B_);
    tc_attn_all<<<agrid, 256>>>();

    split_kernel<<<(nX4 + 255) / 256, 256>>>(ap, ah, al, nX4);
    split_kernel<<<(nW4 + 255) / 256, 256>>>(Wo, wh, wl, nW4);
    gemm_bf16x3_kernel<<<ggrid, 256, GEMM_SMEM>>>(ah, al, wh, wl, bo, out, M_, C_, C_);
}

// round 17
// speedup vs baseline: 1.0732x; 1.0093x over previous
#include <cuda_runtime.h>
#include <cuda_bf16.h>
#include <stdint.h>
#include <math.h>

typedef unsigned int u32;

#define B_  2
#define T_  2048
#define C_  1024
#define H_  16
#define HS_ 64
#define NB_ 32
#define BLK_ 64
#define NSEL_ 8
#define WSZ_ 128
#define M_  (B_*T_)

// ---------------- device scratch ----------------
__device__ float g_q[B_*T_*C_];
__device__ float g_k[B_*T_*C_];
__device__ float g_v[B_*T_*C_];
__device__ float g_gates[B_*T_*3];
__device__ float g_krep[B_*H_*NB_*HS_];
__device__ float g_vcmp[B_*H_*NB_*HS_];
__device__ float g_qbar_part[B_*H_*8*HS_];
__device__ int   g_topidx[B_*H_*NSEL_];
__device__ float g_selk[B_*H_*NSEL_*BLK_*HS_];
__device__ float g_selv[B_*H_*NSEL_*BLK_*HS_];

__device__ __nv_bfloat16 g_xh[M_*C_];
__device__ __nv_bfloat16 g_xl[M_*C_];
__device__ __nv_bfloat16 g_ah[M_*C_];   // attention output hi (written by attention epilogue)
__device__ __nv_bfloat16 g_al[M_*C_];   // attention output lo
__device__ __nv_bfloat16 g_wh[C_*C_];
__device__ __nv_bfloat16 g_wl[C_*C_];

// ---------------- helpers ----------------
__device__ __forceinline__ u32 smem_u32(const void* p) {
    u32 a;
    asm("{ .reg .u64 t; cvta.to.shared.u64 t, %1; cvt.u32.u64 %0, t; }" : "=r"(a) : "l"(p));
    return a;
}
__device__ __forceinline__ void cp16s(u32 saddr, const void* g) {
    asm volatile("cp.async.cg.shared.global [%0], [%1], 16;\n" :: "r"(saddr), "l"(g));
}
__device__ __forceinline__ void ldsm_x4(u32* r, u32 addr) {
    asm volatile("ldmatrix.sync.aligned.m8n8.x4.shared.b16 {%0,%1,%2,%3}, [%4];"
        : "=r"(r[0]), "=r"(r[1]), "=r"(r[2]), "=r"(r[3]) : "r"(addr));
}
__device__ __forceinline__ void ldsm_x4_t(u32* r, u32 addr) {
    asm volatile("ldmatrix.sync.aligned.m8n8.x4.trans.shared.b16 {%0,%1,%2,%3}, [%4];"
        : "=r"(r[0]), "=r"(r[1]), "=r"(r[2]), "=r"(r[3]) : "r"(addr));
}
__device__ __forceinline__ void mma16816(float* d, const u32* a, const u32* b) {
    asm volatile(
        "mma.sync.aligned.m16n8k16.row.col.f32.bf16.bf16.f32 "
        "{%0,%1,%2,%3},{%4,%5,%6,%7},{%8,%9},{%0,%1,%2,%3};"
        : "+f"(d[0]), "+f"(d[1]), "+f"(d[2]), "+f"(d[3])
        : "r"(a[0]), "r"(a[1]), "r"(a[2]), "r"(a[3]), "r"(b[0]), "r"(b[1]));
}
__device__ __forceinline__ u32 pack_hi2(float a, float b) {
    __nv_bfloat162 t = __halves2bfloat162(__float2bfloat16(a), __float2bfloat16(b));
    return *(u32*)&t;
}
__device__ __forceinline__ u32 pack_lo2(float a, float b) {
    __nv_bfloat16 ha = __float2bfloat16(a), hb = __float2bfloat16(b);
    __nv_bfloat162 t = __halves2bfloat162(
        __float2bfloat16(a - __bfloat162float(ha)),
        __float2bfloat16(b - __bfloat162float(hb)));
    return *(u32*)&t;
}

// ---------------- fp32 -> bf16 hi/lo split ----------------
__global__ void split_kernel(const float* __restrict__ src,
                             __nv_bfloat16* __restrict__ hi,
                             __nv_bfloat16* __restrict__ lo, int n4)
{
    int i = blockIdx.x * blockDim.x + threadIdx.x;
    if (i >= n4) return;
    float4 v = ((const float4*)src)[i];
    __nv_bfloat16 h0 = __float2bfloat16(v.x);
    __nv_bfloat16 h1 = __float2bfloat16(v.y);
    __nv_bfloat16 h2 = __float2bfloat16(v.z);
    __nv_bfloat16 h3 = __float2bfloat16(v.w);
    __nv_bfloat16 l0 = __float2bfloat16(v.x - __bfloat162float(h0));
    __nv_bfloat16 l1 = __float2bfloat16(v.y - __bfloat162float(h1));
    __nv_bfloat16 l2 = __float2bfloat16(v.z - __bfloat162float(h2));
    __nv_bfloat16 l3 = __float2bfloat16(v.w - __bfloat162float(h3));
    __nv_bfloat162* hp = (__nv_bfloat162*)hi;
    __nv_bfloat162* lp = (__nv_bfloat162*)lo;
    hp[i*2]   = __halves2bfloat162(h0, h1);
    hp[i*2+1] = __halves2bfloat162(h2, h3);
    lp[i*2]   = __halves2bfloat162(l0, l1);
    lp[i*2+1] = __halves2bfloat162(l2, l3);
}

// ---------------- GEMM: BK=32, 2-stage cp.async, term-major MMAs (R13-proven) ----------------
#define BK3 32
#define A_ROW 40
#define B_ROW 136
#define A_STG (128 * A_ROW)
#define B_STG (32 * B_ROW)
#define GEMM_SMEM ((4 * A_STG + 4 * B_STG) * 2)   // 75776 bytes

__global__ void __launch_bounds__(256) gemm_bf16x3_kernel(
    const __nv_bfloat16* __restrict__ Ah, const __nv_bfloat16* __restrict__ Al,
    const __nv_bfloat16* __restrict__ Bh, const __nv_bfloat16* __restrict__ Bl,
    const float* __restrict__ bias, float* __restrict__ C,
    int M, int N, int K)
{
    extern __shared__ __align__(16) __nv_bfloat16 sm[];
    __nv_bfloat16* sAh = sm;
    __nv_bfloat16* sAl = sm + 2 * A_STG;
    __nv_bfloat16* sBh = sm + 4 * A_STG;
    __nv_bfloat16* sBl = sm + 4 * A_STG + 2 * B_STG;

    int tid = threadIdx.x;
    int lane = tid & 31, warp = tid >> 5;
    int wm = warp >> 1, wn = warp & 1;
    int bm0 = blockIdx.y * 128, bn0 = blockIdx.x * 128;

    int ar0 = tid >> 1,  ac0 = (tid & 1) << 3;
    int ac1 = ac0 + 16;
    int br0 = tid >> 4,  bc0 = (tid & 15) << 3;
    int br1 = br0 + 16;
    const __nv_bfloat16* pAh0 = Ah + (size_t)(bm0 + ar0) * K + ac0;
    const __nv_bfloat16* pAl0 = Al + (size_t)(bm0 + ar0) * K + ac0;
    const __nv_bfloat16* pAh1 = Ah + (size_t)(bm0 + ar0) * K + ac1;
    const __nv_bfloat16* pAl1 = Al + (size_t)(bm0 + ar0) * K + ac1;
    const __nv_bfloat16* pBh0 = Bh + (size_t)br0 * N + bn0 + bc0;
    const __nv_bfloat16* pBl0 = Bl + (size_t)br0 * N + bn0 + bc0;
    const __nv_bfloat16* pBh1 = Bh + (size_t)br1 * N + bn0 + bc0;
    const __nv_bfloat16* pBl1 = Bl + (size_t)br1 * N + bn0 + bc0;
    const u32 a0o = (u32)(ar0 * A_ROW + ac0) * 2;
    const u32 a1o = (u32)(ar0 * A_ROW + ac1) * 2;
    const u32 b0o = (u32)(br0 * B_ROW + bc0) * 2;
    const u32 b1o = (u32)(br1 * B_ROW + bc0) * 2;
    const u32 sAhB = smem_u32(sAh), sAlB = smem_u32(sAl);
    const u32 sBhB = smem_u32(sBh), sBlB = smem_u32(sBl);

    float acc[2][8][4];
#pragma unroll
    for (int mt = 0; mt < 2; mt++)
#pragma unroll
        for (int nt = 0; nt < 8; nt++)
#pragma unroll
            for (int r = 0; r < 4; r++) acc[mt][nt][r] = 0.f;

    const int NK = K / BK3;

#define LOADK(stage, kc) do { \
    u32 as = (u32)(stage) * (A_STG * 2), bs = (u32)(stage) * (B_STG * 2); \
    int ko = (kc) * BK3; \
    cp16s(sAhB + as + a0o, pAh0 + ko); \
    cp16s(sAhB + as + a1o, pAh1 + ko); \
    cp16s(sAlB + as + a0o, pAl0 + ko); \
    cp16s(sAlB + as + a1o, pAl1 + ko); \
    cp16s(sBhB + bs + b0o, pBh0 + (size_t)ko * N); \
    cp16s(sBhB + bs + b1o, pBh1 + (size_t)ko * N); \
    cp16s(sBlB + bs + b0o, pBl0 + (size_t)ko * N); \
    cp16s(sBlB + bs + b1o, pBl1 + (size_t)ko * N); \
    asm volatile("cp.async.commit_group;\n" ::: "memory"); \
} while (0)

    LOADK(0, 0);

    for (int k = 0; k < NK; k++) {
        int cur = k & 1;
        if (k + 1 < NK) {
            LOADK(1 - cur, k + 1);
            asm volatile("cp.async.wait_group 1;\n" ::: "memory");
        } else {
            asm volatile("cp.async.wait_group 0;\n" ::: "memory");
        }
        __syncthreads();

        u32 aBase = (u32)cur * (A_STG * 2);
        u32 bBase = (u32)cur * (B_STG * 2);
#pragma unroll
        for (int ks = 0; ks < 2; ks++) {
            u32 ah[2][4], al[2][4];
#pragma unroll
            for (int mt = 0; mt < 2; mt++) {
                int row = wm * 32 + mt * 16 + (lane & 15);
                int col = ks * 16 + ((lane >> 4) << 3);
                u32 o = (u32)(row * A_ROW + col) * 2;
                ldsm_x4(ah[mt], sAhB + aBase + o);
                ldsm_x4(al[mt], sAlB + aBase + o);
            }
#pragma unroll
            for (int np = 0; np < 4; np++) {
                int krow = ks * 16 + (lane & 7) + (lane & 8);
                int ncol = wn * 64 + np * 16 + ((lane >> 4) << 3);
                u32 o = (u32)(krow * B_ROW + ncol) * 2;
                u32 bh[4], bl[4];
                ldsm_x4_t(bh, sBhB + bBase + o);
                ldsm_x4_t(bl, sBlB + bBase + o);
#pragma unroll
                for (int mt = 0; mt < 2; mt++)
#pragma unroll
                    for (int t = 0; t < 2; t++)
                        mma16816(acc[mt][np * 2 + t], ah[mt], &bh[t * 2]);
#pragma unroll
                for (int mt = 0; mt < 2; mt++)
#pragma unroll
                    for (int t = 0; t < 2; t++)
                        mma16816(acc[mt][np * 2 + t], ah[mt], &bl[t * 2]);
#pragma unroll
                for (int mt = 0; mt < 2; mt++)
#pragma unroll
                    for (int t = 0; t < 2; t++)
                        mma16816(acc[mt][np * 2 + t], al[mt], &bh[t * 2]);
            }
        }
        __syncthreads();
    }
#undef LOADK

    int grp = lane >> 2, tg = lane & 3;
#pragma unroll
    for (int mt = 0; mt < 2; mt++) {
#pragma unroll
        for (int nt = 0; nt < 8; nt++) {
            int row = bm0 + wm * 32 + mt * 16 + grp;
            int col = bn0 + wn * 64 + nt * 8 + tg * 2;
            float b0 = bias[col], b1 = bias[col + 1];
            float* c0 = C + (size_t)row * N + col;
            float* c1 = C + (size_t)(row + 8) * N + col;
            c0[0] = acc[mt][nt][0] + b0;
            c0[1] = acc[mt][nt][1] + b1;
            c1[0] = acc[mt][nt][2] + b0;
            c1[1] = acc[mt][nt][3] + b1;
        }
    }
}

// ---------------- gates ----------------
__global__ void gates_kernel(const float* __restrict__ x,
                             const float* __restrict__ Wg,
                             const float* __restrict__ bg)
{
    int gidx = blockIdx.x * blockDim.x + threadIdx.x;
    int w = gidx >> 5, lane = gidx & 31;
    if (w >= B_ * T_) return;
    const float* xr = x + (size_t)w * C_;
    float s0 = 0, s1 = 0, s2 = 0;
    for (int c = lane; c < C_; c += 32) {
        float xv = xr[c];
        s0 += xv * Wg[c * 3 + 0];
        s1 += xv * Wg[c * 3 + 1];
        s2 += xv * Wg[c * 3 + 2];
    }
#pragma unroll
    for (int o = 16; o; o >>= 1) {
        s0 += __shfl_xor_sync(0xffffffffu, s0, o);
        s1 += __shfl_xor_sync(0xffffffffu, s1, o);
        s2 += __shfl_xor_sync(0xffffffffu, s2, o);
    }
    if (lane == 0) {
        s0 += bg[0]; s1 += bg[1]; s2 += bg[2];
        float mx = fmaxf(s0, fmaxf(s1, s2));
        float e0 = __expf(s0 - mx), e1 = __expf(s1 - mx), e2 = __expf(s2 - mx);
        float inv = 1.f / (e0 + e1 + e2);
        g_gates[w * 3 + 0] = e0 * inv;
        g_gates[w * 3 + 1] = e1 * inv;
        g_gates[w * 3 + 2] = e2 * inv;
    }
}

// ---------------- per-block mean of K and V ----------------
__global__ void blockmean_kernel()
{
    int idx = blockIdx.x * blockDim.x + threadIdx.x;
    if (idx >= B_ * H_ * NB_ * HS_) return;
    int d = idx & 63;
    int n = (idx >> 6) & 31;
    int h = (idx >> 11) & 15;
    int b = idx >> 15;
    const float* kp = g_k + ((size_t)(b * T_ + n * BLK_)) * C_ + h * HS_ + d;
    const float* vp = g_v + ((size_t)(b * T_ + n * BLK_)) * C_ + h * HS_ + d;
    float sk = 0.f, sv = 0.f;
    for (int j = 0; j < BLK_; j++) {
        sk += kp[(size_t)j * C_];
        sv += vp[(size_t)j * C_];
    }
    g_krep[idx] = sk * (1.f / BLK_);
    g_vcmp[idx] = sv * (1.f / BLK_);
}

// ---------------- qbar phase 1 ----------------
__global__ void qbar1_kernel()
{
    int bh = blockIdx.x >> 3, chunk = blockIdx.x & 7;
    int b = bh >> 4, h = bh & 15;
    int warp = threadIdx.x >> 5, lane = threadIdx.x & 31;
    float a0 = 0.f, a1 = 0.f;
    int t0 = chunk * 256;
    for (int t = t0 + warp; t < t0 + 256; t += 8) {
        const float* qr = g_q + ((size_t)(b * T_ + t)) * C_ + h * HS_;
        float x0 = qr[lane], x1 = qr[lane + 32];
        float ss = x0 * x0 + x1 * x1;
#pragma unroll
        for (int o = 16; o; o >>= 1) ss += __shfl_xor_sync(0xffffffffu, ss, o);
        float inv = 1.f / fmaxf(sqrtf(ss), 1e-8f);
        a0 += x0 * inv;
        a1 += x1 * inv;
    }
    __shared__ float acc[64];
    if (threadIdx.x < 64) acc[threadIdx.x] = 0.f;
    __syncthreads();
    atomicAdd(&acc[lane], a0);
    atomicAdd(&acc[lane + 32], a1);
    __syncthreads();
    if (threadIdx.x < 64)
        g_qbar_part[(size_t)blockIdx.x * 64 + threadIdx.x] = acc[threadIdx.x];
}

// ---------------- fused qbar phase 2 + top-8 (one block per bh) ----------------
__global__ void qbar2_topk_kernel()
{
    int bh = blockIdx.x;
    int tid = threadIdx.x;   // 64 threads
    __shared__ float qb[64];
    __shared__ float sc[NB_];

    float s = 0.f;
#pragma unroll
    for (int c = 0; c < 8; c++)
        s += g_qbar_part[((size_t)bh * 8 + c) * 64 + tid];
    qb[tid] = s;
    __syncthreads();

    if (tid < NB_) {
        const float* kr = g_krep + ((size_t)bh * NB_ + tid) * HS_;
        float dot = 0.f, ss = 0.f;
        for (int d = 0; d < HS_; d++) {
            float kv = kr[d];
            dot += kv * qb[d];
            ss += kv * kv;
        }
        sc[tid] = dot / fmaxf(sqrtf(ss), 1e-8f);
    }
    __syncthreads();
    if (tid == 0) {
        bool used[NB_];
        for (int m = 0; m < NB_; m++) used[m] = false;
        for (int s2 = 0; s2 < NSEL_; s2++) {
            float best = -1e30f; int bi = 0;
            for (int m = 0; m < NB_; m++)
                if (!used[m] && sc[m] > best) { best = sc[m]; bi = m; }
            used[bi] = true;
            g_topidx[bh * NSEL_ + s2] = bi;
        }
    }
}

// ---------------- gather selected K/V ----------------
__global__ void gather_kernel()
{
    int idx = blockIdx.x * blockDim.x + threadIdx.x;
    if (idx >= B_ * H_ * NSEL_ * BLK_ * HS_) return;
    int d = idx & 63;
    int s = (idx >> 6) & 511;
    int h = (idx >> 15) & 15;
    int b = idx >> 19;
    int blk = g_topidx[(b * H_ + h) * NSEL_ + (s >> 6)];
    int row = blk * BLK_ + (s & 63);
    size_t src = ((size_t)(b * T_ + row)) * C_ + h * HS_ + d;
    g_selk[idx] = g_k[src];
    g_selv[idx] = g_v[src];
}

// ---------------- merged tensor-core attention: 128 queries/block, 8 warps ----------------
// Epilogue writes bf16 hi/lo planes directly (== split(gated sum)).
__global__ void __launch_bounds__(256) tc_attn_all()
{
    const int qt = blockIdx.x;
    const int h = blockIdx.y, b = blockIdx.z;
    const int q0 = qt * 128;
    const int lane = threadIdx.x & 31, warp = threadIdx.x >> 5;
    const int g = lane >> 2, tg = lane & 3;
    const int i0 = q0 + warp * 16 + g;
    const int i1 = i0 + 8;

    __shared__ __align__(16) __nv_bfloat16 sKh[64][72];
    __shared__ __align__(16) __nv_bfloat16 sKl[64][72];
    __shared__ __align__(16) __nv_bfloat16 sVh[64][72];
    __shared__ __align__(16) __nv_bfloat16 sVl[64][72];

    u32 qh[4][4], ql[4][4];
    {
        const float* qr0 = g_q + ((size_t)(b * T_ + i0)) * C_ + h * HS_;
        const float* qr1 = g_q + ((size_t)(b * T_ + i1)) * C_ + h * HS_;
#pragma unroll
        for (int kk = 0; kk < 4; kk++) {
            int c = kk * 16 + tg * 2;
            qh[kk][0] = pack_hi2(qr0[c], qr0[c + 1]);
            ql[kk][0] = pack_lo2(qr0[c], qr0[c + 1]);
            qh[kk][1] = pack_hi2(qr1[c], qr1[c + 1]);
            ql[kk][1] = pack_lo2(qr1[c], qr1[c + 1]);
            qh[kk][2] = pack_hi2(qr0[c + 8], qr0[c + 9]);
            ql[kk][2] = pack_lo2(qr0[c + 8], qr0[c + 9]);
            qh[kk][3] = pack_hi2(qr1[c + 8], qr1[c + 9]);
            ql[kk][3] = pack_lo2(qr1[c + 8], qr1[c + 9]);
        }
    }

    float Of[8][4];
#pragma unroll
    for (int nt = 0; nt < 8; nt++)
#pragma unroll
        for (int r = 0; r < 4; r++) Of[nt][r] = 0.f;

    for (int mode = 0; mode < 3; mode++) {
        float O[8][4];
#pragma unroll
        for (int nt = 0; nt < 8; nt++)
#pragma unroll
            for (int r = 0; r < 4; r++) O[nt][r] = 0.f;
        float m0 = -1e30f, m1 = -1e30f, l0 = 0.f, l1 = 0.f;

        int kt0, kt1, krows, ntmax;
        if (mode == 0)      { kt0 = (qt >= 1 ? 2 * qt - 2 : 0); kt1 = 2 * qt + 1; krows = 64; ntmax = 8; }
        else if (mode == 1) { kt0 = 0; int m1i = 2 * qt + 1; kt1 = (m1i < 7 ? m1i : 7); krows = 64; ntmax = 8; }
        else                { kt0 = 0; kt1 = 0; krows = 32; ntmax = 4; }

        for (int kt = kt0; kt <= kt1; kt++) {
            const float* ksrc; const float* vsrc; int kstride;
            if (mode == 0) {
                ksrc = g_k + ((size_t)(b * T_ + kt * 64)) * C_ + h * HS_;
                vsrc = g_v + ((size_t)(b * T_ + kt * 64)) * C_ + h * HS_;
                kstride = C_;
            } else if (mode == 1) {
                ksrc = g_selk + ((size_t)((b * H_ + h) * 512 + kt * 64)) * HS_;
                vsrc = g_selv + ((size_t)((b * H_ + h) * 512 + kt * 64)) * HS_;
                kstride = HS_;
            } else {
                ksrc = g_krep + ((size_t)(b * H_ + h) * NB_) * HS_;
                vsrc = g_vcmp + ((size_t)(b * H_ + h) * NB_) * HS_;
                kstride = HS_;
            }
            for (int idx = threadIdx.x; idx < krows * 16; idx += 256) {
                int r = idx >> 4, c = (idx & 15) * 4;
                float4 kv = *(const float4*)(ksrc + (size_t)r * kstride + c);
                float4 vv = *(const float4*)(vsrc + (size_t)r * kstride + c);
                __nv_bfloat16 h0 = __float2bfloat16(kv.x), h1 = __float2bfloat16(kv.y);
                __nv_bfloat16 h2 = __float2bfloat16(kv.z), h3 = __float2bfloat16(kv.w);
                sKh[r][c] = h0; sKh[r][c+1] = h1; sKh[r][c+2] = h2; sKh[r][c+3] = h3;
                sKl[r][c]   = __float2bfloat16(kv.x - __bfloat162float(h0));
                sKl[r][c+1] = __float2bfloat16(kv.y - __bfloat162float(h1));
                sKl[r][c+2] = __float2bfloat16(kv.z - __bfloat162float(h2));
                sKl[r][c+3] = __float2bfloat16(kv.w - __bfloat162float(h3));
                h0 = __float2bfloat16(vv.x); h1 = __float2bfloat16(vv.y);
                h2 = __float2bfloat16(vv.z); h3 = __float2bfloat16(vv.w);
                sVh[r][c] = h0; sVh[r][c+1] = h1; sVh[r][c+2] = h2; sVh[r][c+3] = h3;
                sVl[r][c]   = __float2bfloat16(vv.x - __bfloat162float(h0));
                sVl[r][c+1] = __float2bfloat16(vv.y - __bfloat162float(h1));
                sVl[r][c+2] = __float2bfloat16(vv.z - __bfloat162float(h2));
                sVl[r][c+3] = __float2bfloat16(vv.w - __bfloat162float(h3));
            }
            __syncthreads();

            float S[8][4];
#pragma unroll
            for (int nt = 0; nt < 8; nt++)
#pragma unroll
                for (int r = 0; r < 4; r++) S[nt][r] = 0.f;

#pragma unroll
            for (int kk = 0; kk < 4; kk++) {
                for (int ntp = 0; ntp < ntmax / 2; ntp++) {
                    int row = ntp * 16 + ((lane >> 4) << 3) + (lane & 7);
                    int col = kk * 16 + (((lane >> 3) & 1) << 3);
                    u32 kh2[4], kl2[4];
                    ldsm_x4(kh2, smem_u32(&sKh[row][col]));
                    ldsm_x4(kl2, smem_u32(&sKl[row][col]));
#pragma unroll
                    for (int t = 0; t < 2; t++)
                        mma16816(S[ntp * 2 + t], qh[kk], &kh2[t * 2]);
#pragma unroll
                    for (int t = 0; t < 2; t++)
                        mma16816(S[ntp * 2 + t], qh[kk], &kl2[t * 2]);
#pragma unroll
                    for (int t = 0; t < 2; t++)
                        mma16816(S[ntp * 2 + t], ql[kk], &kh2[t * 2]);
                }
            }

            const int tilebase = kt * 64;
            for (int nt = 0; nt < ntmax; nt++) {
                int c0 = tilebase + nt * 8 + tg * 2;
                int c1 = c0 + 1;
                bool v00 = (c0 <= i0), v01 = (c1 <= i0), v10 = (c0 <= i1), v11 = (c1 <= i1);
                if (mode == 0) {
                    v00 = v00 && (i0 - c0 <= WSZ_);
                    v01 = v01 && (i0 - c1 <= WSZ_);
                    v10 = v10 && (i1 - c0 <= WSZ_);
                    v11 = v11 && (i1 - c1 <= WSZ_);
                }
                S[nt][0] = v00 ? S[nt][0] * 0.125f : -1e30f;
                S[nt][1] = v01 ? S[nt][1] * 0.125f : -1e30f;
                S[nt][2] = v10 ? S[nt][2] * 0.125f : -1e30f;
                S[nt][3] = v11 ? S[nt][3] * 0.125f : -1e30f;
            }

            float mx0 = -1e30f, mx1 = -1e30f;
            for (int nt = 0; nt < ntmax; nt++) {
                mx0 = fmaxf(mx0, fmaxf(S[nt][0], S[nt][1]));
                mx1 = fmaxf(mx1, fmaxf(S[nt][2], S[nt][3]));
            }
            mx0 = fmaxf(mx0, __shfl_xor_sync(0xffffffffu, mx0, 1));
            mx0 = fmaxf(mx0, __shfl_xor_sync(0xffffffffu, mx0, 2));
            mx1 = fmaxf(mx1, __shfl_xor_sync(0xffffffffu, mx1, 1));
            mx1 = fmaxf(mx1, __shfl_xor_sync(0xffffffffu, mx1, 2));

            float mn0 = fmaxf(m0, mx0), mn1 = fmaxf(m1, mx1);
            float sc0 = __expf(m0 - mn0), sc1 = __expf(m1 - mn1);
            m0 = mn0; m1 = mn1;

            float la0 = 0.f, la1 = 0.f;
            for (int nt = 0; nt < ntmax; nt++) {
                S[nt][0] = __expf(S[nt][0] - mn0);
                S[nt][1] = __expf(S[nt][1] - mn0);
                S[nt][2] = __expf(S[nt][2] - mn1);
                S[nt][3] = __expf(S[nt][3] - mn1);
                la0 += S[nt][0] + S[nt][1];
                la1 += S[nt][2] + S[nt][3];
            }
            la0 += __shfl_xor_sync(0xffffffffu, la0, 1);
            la0 += __shfl_xor_sync(0xffffffffu, la0, 2);
            la1 += __shfl_xor_sync(0xffffffffu, la1, 1);
            la1 += __shfl_xor_sync(0xffffffffu, la1, 2);
            l0 = l0 * sc0 + la0;
            l1 = l1 * sc1 + la1;

#pragma unroll
            for (int nt = 0; nt < 8; nt++) {
                O[nt][0] *= sc0; O[nt][1] *= sc0;
                O[nt][2] *= sc1; O[nt][3] *= sc1;
            }

            for (int kk = 0; kk < ntmax / 2; kk++) {
                u32 ph[4], pl[4];
                ph[0] = pack_hi2(S[2*kk][0],   S[2*kk][1]);
                pl[0] = pack_lo2(S[2*kk][0],   S[2*kk][1]);
                ph[1] = pack_hi2(S[2*kk][2],   S[2*kk][3]);
                pl[1] = pack_lo2(S[2*kk][2],   S[2*kk][3]);
                ph[2] = pack_hi2(S[2*kk+1][0], S[2*kk+1][1]);
                pl[2] = pack_lo2(S[2*kk+1][0], S[2*kk+1][1]);
                ph[3] = pack_hi2(S[2*kk+1][2], S[2*kk+1][3]);
                pl[3] = pack_lo2(S[2*kk+1][2], S[2*kk+1][3]);
#pragma unroll
                for (int ntp = 0; ntp < 4; ntp++) {
                    int krow = kk * 16 + (lane & 7) + (lane & 8);
                    int ncol = ntp * 16 + ((lane >> 4) << 3);
                    u32 vh2[4], vl2[4];
                    ldsm_x4_t(vh2, smem_u32(&sVh[krow][ncol]));
                    ldsm_x4_t(vl2, smem_u32(&sVl[krow][ncol]));
#pragma unroll
                    for (int t = 0; t < 2; t++)
                        mma16816(O[ntp * 2 + t], ph, &vh2[t * 2]);
#pragma unroll
                    for (int t = 0; t < 2; t++)
                        mma16816(O[ntp * 2 + t], ph, &vl2[t * 2]);
#pragma unroll
                    for (int t = 0; t < 2; t++)
                        mma16816(O[ntp * 2 + t], pl, &vh2[t * 2]);
                }
            }
            __syncthreads();
        }

        float g0 = g_gates[(b * T_ + i0) * 3 + mode];
        float g1 = g_gates[(b * T_ + i1) * 3 + mode];
        float inv0 = g0 / l0, inv1 = g1 / l1;
#pragma unroll
        for (int nt = 0; nt < 8; nt++) {
            Of[nt][0] += O[nt][0] * inv0;
            Of[nt][1] += O[nt][1] * inv0;
            Of[nt][2] += O[nt][2] * inv1;
            Of[nt][3] += O[nt][3] * inv1;
        }
    }

    // epilogue: write bf16 hi/lo planes directly (numerically == split(gated sum))
    size_t o0 = ((size_t)(b * T_ + i0)) * C_ + h * HS_;
    size_t o1 = ((size_t)(b * T_ + i1)) * C_ + h * HS_;
#pragma unroll
    for (int nt = 0; nt < 8; nt++) {
        int c = nt * 8 + tg * 2;
        *(u32*)(g_ah + o0 + c) = pack_hi2(Of[nt][0], Of[nt][1]);
        *(u32*)(g_al + o0 + c) = pack_lo2(Of[nt][0], Of[nt][1]);
        *(u32*)(g_ah + o1 + c) = pack_hi2(Of[nt][2], Of[nt][3]);
        *(u32*)(g_al + o1 + c) = pack_lo2(Of[nt][2], Of[nt][3]);
    }
}

// ---------------- host launch ----------------
extern "C" void kernel_launch(void* const* d_in, const int* in_sizes, int n_in,
                              void* d_out, int out_size)
{
    const float* x  = (const float*)d_in[0];
    const float* Wq = (const float*)d_in[1];
    const float* bq = (const float*)d_in[2];
    const float* Wk = (const float*)d_in[3];
    const float* bk = (const float*)d_in[4];
    const float* Wv = (const float*)d_in[5];
    const float* bv = (const float*)d_in[6];
    const float* Wo = (const float*)d_in[7];
    const float* bo = (const float*)d_in[8];
    const float* Wg = (const float*)d_in[9];
    const float* bg = (const float*)d_in[10];
    float* out = (float*)d_out;

    float *qp, *kp, *vp;
    cudaGetSymbolAddress((void**)&qp, g_q);
    cudaGetSymbolAddress((void**)&kp, g_k);
    cudaGetSymbolAddress((void**)&vp, g_v);
    __nv_bfloat16 *xh, *xl, *ah, *al, *wh, *wl;
    cudaGetSymbolAddress((void**)&xh, g_xh);
    cudaGetSymbolAddress((void**)&xl, g_xl);
    cudaGetSymbolAddress((void**)&ah, g_ah);
    cudaGetSymbolAddress((void**)&al, g_al);
    cudaGetSymbolAddress((void**)&wh, g_wh);
    cudaGetSymbolAddress((void**)&wl, g_wl);

    cudaFuncSetAttribute(gemm_bf16x3_kernel, cudaFuncAttributeMaxDynamicSharedMemorySize, GEMM_SMEM);

    const int nX4 = (M_ * C_) / 4;
    const int nW4 = (C_ * C_) / 4;

    dim3 ggrid(C_ / 128, M_ / 128);

    split_kernel<<<(nX4 + 255) / 256, 256>>>(x, xh, xl, nX4);

    split_kernel<<<(nW4 + 255) / 256, 256>>>(Wq, wh, wl, nW4);
    gemm_bf16x3_kernel<<<ggrid, 256, GEMM_SMEM>>>(xh, xl, wh, wl, bq, qp, M_, C_, C_);
    split_kernel<<<(nW4 + 255) / 256, 256>>>(Wk, wh, wl, nW4);
    gemm_bf16x3_kernel<<<ggrid, 256, GEMM_SMEM>>>(xh, xl, wh, wl, bk, kp, M_, C_, C_);
    split_kernel<<<(nW4 + 255) / 256, 256>>>(Wv, wh, wl, nW4);
    gemm_bf16x3_kernel<<<ggrid, 256, GEMM_SMEM>>>(xh, xl, wh, wl, bv, vp, M_, C_, C_);

    gates_kernel<<<(B_ * T_ * 32) / 256, 256>>>(x, Wg, bg);
    blockmean_kernel<<<(B_ * H_ * NB_ * HS_) / 256, 256>>>();
    qbar1_kernel<<<B_ * H_ * 8, 256>>>();
    qbar2_topk_kernel<<<B_ * H_, 64>>>();
    gather_kernel<<<(B_ * H_ * NSEL_ * BLK_ * HS_) / 256, 256>>>();

    dim3 agrid(T_ / 128, H_, B_);
    tc_attn_all<<<agrid, 256>>>();

    split_kernel<<<(nW4 + 255) / 256, 256>>>(Wo, wh, wl, nW4);
    gemm_bf16x3_kernel<<<ggrid, 256, GEMM_SMEM>>>(ah, al, wh, wl, bo, out, M_, C_, C_);
}